// round 10
// baseline (speedup 1.0000x reference)
#include <cuda_runtime.h>
#include <cstdint>

#define D_IN   128
#define D_OUT  64
#define D_EDGE 11
#define NMAX   100000
#define EMAX   1000000
#define NEG_SLOPE 0.2f
#define SCAN_BLK 512

// Scratch: ONLY referenced from device code (host-side use of a __device__
// symbol passes the host shadow address; ATS silently dereferences it).
__device__ float g_xl[(size_t)NMAX * D_OUT];     // x @ W_l
__device__ float g_xr[(size_t)NMAX * D_OUT];     // x @ W_r
__device__ float g_ex[EMAX];                     // exp(logit) per edge
__device__ int2  g_sd[EMAX];                     // decoded (src, dst)
__device__ int2  g_csr[EMAX];                    // CSR payload: (src, eid)
__device__ int   g_cnt[NMAX];                    // in-degree counts
__device__ int   g_off[NMAX];                    // CSR offsets
__device__ int   g_cursor[NMAX];                 // scatter cursors
__device__ int   g_bsum[(NMAX + SCAN_BLK - 1) / SCAN_BLK];
__device__ int   g_is64;
__device__ int   g_diag;

// ---------------------------------------------------------------------------
// Zero counts; detect int32 vs int64 edge_index (int64 values < 2^31 ->
// hi words of first 64 entries all zero; P[false positive] ~ 1e-320).
// ---------------------------------------------------------------------------
__global__ void init_kernel(const int* __restrict__ ei, int E, int n) {
    int stride = gridDim.x * blockDim.x;
    int tid0 = blockIdx.x * blockDim.x + threadIdx.x;
    if (tid0 == 0) {
        g_diag = 0;
        int nz_hi = 0;
        int lim = (E > 64) ? 64 : E;
        for (int k = 0; k < lim; k++)
            if (ei[2 * k + 1] != 0) nz_hi++;
        g_is64 = (nz_hi == 0) ? 1 : 0;
    }
    for (int i = tid0; i < n; i += stride) g_cnt[i] = 0;
}

__global__ void set_diag_kernel(int bits) {
    if (threadIdx.x == 0) atomicOr(&g_diag, bits);
}

// Decode edge_index -> (src,dst) int2 + per-dst counts.
__global__ void decode_kernel(const int* __restrict__ ei, int E, int n) {
    const int is64 = g_is64;
    int stride = gridDim.x * blockDim.x;
    for (int i = blockIdx.x * blockDim.x + threadIdx.x; i < E; i += stride) {
        int s, d;
        if (is64) { s = ei[2 * i];  d = ei[2 * E + 2 * i]; }
        else      { s = ei[i];      d = ei[E + i]; }
        if ((unsigned)s >= (unsigned)n) { atomicOr(&g_diag, 4); s = 0; }
        if ((unsigned)d >= (unsigned)n) { atomicOr(&g_diag, 4); d = 0; }
        g_sd[i] = make_int2(s, d);
        atomicAdd(&g_cnt[d], 1);
    }
}

// ---- 3-kernel exclusive scan over g_cnt -> g_off (debugged in R6) ----------
__global__ void scanA_kernel(int n) {
    __shared__ int s[SCAN_BLK];
    int t = threadIdx.x;
    int idx = blockIdx.x * SCAN_BLK + t;
    int v = (idx < n) ? g_cnt[idx] : 0;
    s[t] = v; __syncthreads();
    for (int off = 1; off < SCAN_BLK; off <<= 1) {
        int x = (t >= off) ? s[t - off] : 0;
        __syncthreads();
        s[t] += x;
        __syncthreads();
    }
    if (idx < n) g_off[idx] = s[t] - v;          // exclusive
    if (t == SCAN_BLK - 1) g_bsum[blockIdx.x] = s[t];
}

__global__ void scanB_kernel(int nblk) {
    if (threadIdx.x == 0) {
        int run = 0;
        for (int b = 0; b < nblk; b++) { int t = g_bsum[b]; g_bsum[b] = run; run += t; }
    }
}

__global__ void scanC_kernel(int n) {
    int idx = blockIdx.x * SCAN_BLK + threadIdx.x;
    if (idx < n) {
        int o = g_off[idx] + g_bsum[blockIdx.x];
        g_off[idx] = o;
        g_cursor[idx] = o;
    }
}

// Scatter edges into CSR buckets (integer atomics only, ~2M words).
__global__ void scatter_kernel(int E) {
    int stride = gridDim.x * blockDim.x;
    for (int i = blockIdx.x * blockDim.x + threadIdx.x; i < E; i += stride) {
        int2 sd = g_sd[i];
        int pos = atomicAdd(&g_cursor[sd.y], 1);
        g_csr[pos] = make_int2(sd.x, i);
    }
}

__global__ void diag_apply_kernel(float* __restrict__ out, int total) {
    const int diag = g_diag;
    if (diag == 0) return;
    float v = 0.f;
    if (diag & 4) v = 1e16f;
    if (diag & 8) v = 1e20f;
    int stride = gridDim.x * blockDim.x;
    for (int i = blockIdx.x * blockDim.x + threadIdx.x; i < total; i += stride)
        out[i] = v;
}

// ---------------------------------------------------------------------------
// GEMM (R9, measured 59.1us): g_x{l,r}[n,64] = x[n,128] @ W[128,64].
// Bank-conflict-free: thread cg reads smem words cg*4 / 32+cg*4.
// ---------------------------------------------------------------------------
__global__ __launch_bounds__(256) void gemm_kernel(
    const float* __restrict__ x, const float* __restrict__ W,
    int n, int which)
{
    float* __restrict__ out = which ? g_xr : g_xl;   // device-side symbol

    __shared__ float sW[D_IN * D_OUT];  // 32 KB
    for (int i = threadIdx.x; i < D_IN * D_OUT / 4; i += 256) {
        reinterpret_cast<float4*>(sW)[i] = reinterpret_cast<const float4*>(W)[i];
    }
    __syncthreads();

    const int cg   = threadIdx.x & 7;
    const int rg   = threadIdx.x >> 3;
    const int row0 = blockIdx.x * 128 + rg * 4;
    const float4* sW4 = reinterpret_cast<const float4*>(sW);

    float acc0[4][4], acc1[4][4];
#pragma unroll
    for (int r = 0; r < 4; r++)
#pragma unroll
        for (int c = 0; c < 4; c++) { acc0[r][c] = 0.f; acc1[r][c] = 0.f; }

    for (int k = 0; k < D_IN; k += 4) {
        float xk[4][4];
#pragma unroll
        for (int r = 0; r < 4; r++) {
            int row = row0 + r;
            float4 v = make_float4(0.f, 0.f, 0.f, 0.f);
            if (row < n)
                v = *reinterpret_cast<const float4*>(x + (size_t)row * D_IN + k);
            xk[r][0] = v.x; xk[r][1] = v.y; xk[r][2] = v.z; xk[r][3] = v.w;
        }
#pragma unroll
        for (int kk = 0; kk < 4; kk++) {
            const float4 w0 = sW4[(k + kk) * 16 + cg];
            const float4 w1 = sW4[(k + kk) * 16 + 8 + cg];
#pragma unroll
            for (int r = 0; r < 4; r++) {
                const float xv = xk[r][kk];
                acc0[r][0] += xv * w0.x;  acc0[r][1] += xv * w0.y;
                acc0[r][2] += xv * w0.z;  acc0[r][3] += xv * w0.w;
                acc1[r][0] += xv * w1.x;  acc1[r][1] += xv * w1.y;
                acc1[r][2] += xv * w1.z;  acc1[r][3] += xv * w1.w;
            }
        }
    }

#pragma unroll
    for (int r = 0; r < 4; r++) {
        int row = row0 + r;
        if (row < n) {
            *reinterpret_cast<float4*>(out + (size_t)row * D_OUT + cg * 4) =
                make_float4(acc0[r][0], acc0[r][1], acc0[r][2], acc0[r][3]);
            *reinterpret_cast<float4*>(out + (size_t)row * D_OUT + 32 + cg * 4) =
                make_float4(acc1[r][0], acc1[r][1], acc1[r][2], acc1[r][3]);
        }
    }
}

// ---------------------------------------------------------------------------
// Phase A: edge-parallel logit pass. 2 edges/warp, 16 lanes x 4 cols.
//   ex[e] = exp( lrelu(xl[src]+xr[dst]+attr@We) . att )
// One coalesced STG word per edge; NO atomics.
// ---------------------------------------------------------------------------
__global__ __launch_bounds__(256) void phaseA_kernel(
    const float* __restrict__ ea,
    const float* __restrict__ We, const float* __restrict__ att, int E)
{
    const int lane   = threadIdx.x & 31;
    const int half   = lane >> 4;
    const int sub    = lane & 15;
    const int cb     = sub * 4;
    const int hbase  = half << 4;
    const int warp   = (blockIdx.x * blockDim.x + threadIdx.x) >> 5;
    const int nwarps = (gridDim.x * blockDim.x) >> 5;

    float4 wev[D_EDGE];
#pragma unroll
    for (int j = 0; j < D_EDGE; j++)
        wev[j] = *reinterpret_cast<const float4*>(We + j * D_OUT + cb);
    const float4 at = *reinterpret_cast<const float4*>(att + cb);

    for (int e0 = warp * 2; e0 < E; e0 += nwarps * 2) {
        const int  e     = e0 + half;
        const bool valid = (e < E);
        const int  ec    = valid ? e : e0;

        const int2 sd = g_sd[ec];
        const float av = (sub < D_EDGE) ? __ldg(ea + (size_t)ec * D_EDGE + sub) : 0.f;

        const float4 vl = *reinterpret_cast<const float4*>(
            g_xl + (size_t)sd.x * D_OUT + cb);
        const float4 vr = *reinterpret_cast<const float4*>(
            g_xr + (size_t)sd.y * D_OUT + cb);

        float e0c = 0.f, e1c = 0.f, e2c = 0.f, e3c = 0.f;
#pragma unroll
        for (int j = 0; j < D_EDGE; j++) {
            const float aj = __shfl_sync(0xffffffffu, av, hbase + j);
            e0c += aj * wev[j].x;
            e1c += aj * wev[j].y;
            e2c += aj * wev[j].z;
            e3c += aj * wev[j].w;
        }

        float m0 = vl.x + vr.x + e0c;
        float m1 = vl.y + vr.y + e1c;
        float m2 = vl.z + vr.z + e2c;
        float m3 = vl.w + vr.w + e3c;
        m0 = (m0 >= 0.f) ? m0 : NEG_SLOPE * m0;
        m1 = (m1 >= 0.f) ? m1 : NEG_SLOPE * m1;
        m2 = (m2 >= 0.f) ? m2 : NEG_SLOPE * m2;
        m3 = (m3 >= 0.f) ? m3 : NEG_SLOPE * m3;
        float p = m0 * at.x + m1 * at.y + m2 * at.z + m3 * at.w;
#pragma unroll
        for (int o = 8; o > 0; o >>= 1)
            p += __shfl_xor_sync(0xffffffffu, p, o);

        if (valid && sub == 0)
            g_ex[e] = __expf(p);    // max-free softmax weight
    }
}

// ---------------------------------------------------------------------------
// Phase B: warp-per-node gather. Lane owns cols (2*lane, 2*lane+1).
// Loop body has NO shfl/exp/atomics -> fully pipelined independent loads.
//   acc += ex * xl[src];  den += ex (all lanes, redundant);
//   la  += attr[lane]     (lanes 0..10, for self-loop)
// Epilogue: self-loop logit (11 bcast shfls + 5-shfl reduce + 1 exp),
// normalize, single coalesced write. Replaces final_kernel too.
// ---------------------------------------------------------------------------
__global__ __launch_bounds__(256) void phaseB_kernel(
    const float* __restrict__ ea,
    const float* __restrict__ We, const float* __restrict__ att,
    float* __restrict__ out, int n)
{
    const int lane = threadIdx.x & 31;
    const int node = (blockIdx.x * blockDim.x + threadIdx.x) >> 5;
    if (node >= n) return;

    const int start = g_off[node];
    const int deg   = g_cnt[node];

    float a0 = 0.f, a1 = 0.f;   // accumulated message (2 cols)
    float den = 0.f;            // sum of ex (redundant across lanes)
    float la  = 0.f;            // attr sum, lanes 0..10

    for (int k = 0; k < deg; k++) {
        const int2 ce = g_csr[start + k];               // (src, eid) uniform
        const float ex = __ldg(&g_ex[ce.y]);            // uniform 4B
        const float2 vl = *reinterpret_cast<const float2*>(
            g_xl + (size_t)ce.x * D_OUT + 2 * lane);    // 256B coalesced
        if (lane < D_EDGE)
            la += __ldg(ea + (size_t)ce.y * D_EDGE + lane);
        a0 += ex * vl.x;
        a1 += ex * vl.y;
        den += ex;
    }

    // ---- epilogue: self-loop + normalize ----
    float we0[D_EDGE], we1[D_EDGE];
#pragma unroll
    for (int j = 0; j < D_EDGE; j++) {
        float2 w = *reinterpret_cast<const float2*>(We + j * D_OUT + 2 * lane);
        we0[j] = w.x; we1[j] = w.y;
    }
    const float2 at  = *reinterpret_cast<const float2*>(att + 2 * lane);
    const float2 vli = *reinterpret_cast<const float2*>(g_xl + (size_t)node * D_OUT + 2 * lane);
    const float2 vr  = *reinterpret_cast<const float2*>(g_xr + (size_t)node * D_OUT + 2 * lane);

    const float inv_deg = 1.0f / fmaxf((float)deg, 1.0f);
    float e0 = 0.f, e1 = 0.f;
#pragma unroll
    for (int j = 0; j < D_EDGE; j++) {
        const float aj = __shfl_sync(0xffffffffu, la, j) * inv_deg;
        e0 += aj * we0[j];
        e1 += aj * we1[j];
    }

    float m0 = vli.x + vr.x + e0;
    float m1 = vli.y + vr.y + e1;
    m0 = (m0 >= 0.f) ? m0 : NEG_SLOPE * m0;
    m1 = (m1 >= 0.f) ? m1 : NEG_SLOPE * m1;
    float p = m0 * at.x + m1 * at.y;
#pragma unroll
    for (int o = 16; o > 0; o >>= 1)
        p += __shfl_xor_sync(0xffffffffu, p, o);
    const float exs = __expf(p);

    const float invd = 1.0f / (den + exs);
    float2 o;
    o.x = (a0 + exs * vli.x) * invd;
    o.y = (a1 + exs * vli.y) * invd;
    *reinterpret_cast<float2*>(out + (size_t)node * D_OUT + 2 * lane) = o;
}

// ---------------------------------------------------------------------------
extern "C" void kernel_launch(void* const* d_in, const int* in_sizes, int n_in,
                              void* d_out, int out_size)
{
    const float *x = nullptr, *ea = nullptr, *Wl = nullptr, *Wr = nullptr;
    const float *We = nullptr, *att = nullptr;
    const int   *ei = nullptr;
    long long E = 0;
    int n = 0;

    for (int i = 0; i < n_in; i++) {               // pass 1: edge_attr
        long long s = in_sizes[i];
        if (s > 100000 && s % D_EDGE == 0) { ea = (const float*)d_in[i]; E = s / D_EDGE; }
    }
    for (int i = 0; i < n_in; i++) {               // pass 2: everything else
        long long s = in_sizes[i];
        const void* p = d_in[i];
        if (p == (const void*)ea) continue;
        if      (E > 0 && (s == 2 * E || s == 4 * E)) { ei = (const int*)p; }
        else if (s == D_IN * D_OUT)   { if (!Wl) Wl = (const float*)p; else Wr = (const float*)p; }
        else if (s == D_EDGE * D_OUT) { We  = (const float*)p; }
        else if (s == D_OUT)          { att = (const float*)p; }
        else if (s > 100000 && s % D_IN == 0) { x = (const float*)p; n = (int)(s / D_IN); }
    }

    float* out = (float*)d_out;
    const int total_out = out_size;

    if (!x || !ea || !ei || !Wl || !Wr || !We || !att || n <= 0 || E <= 0 ||
        n > NMAX || E > EMAX) {
        set_diag_kernel<<<1, 32>>>(8);
        diag_apply_kernel<<<512, 256>>>(out, total_out);
        return;
    }
    const int Ei = (int)E;
    const int nblk = (n + SCAN_BLK - 1) / SCAN_BLK;

    init_kernel<<<256, 256>>>(ei, Ei, n);
    decode_kernel<<<512, 256>>>(ei, Ei, n);

    scanA_kernel<<<nblk, SCAN_BLK>>>(n);
    scanB_kernel<<<1, 32>>>(nblk);
    scanC_kernel<<<nblk, SCAN_BLK>>>(n);
    scatter_kernel<<<512, 256>>>(Ei);

    gemm_kernel<<<(n + 127) / 128, 256>>>(x, Wl, n, 0);  // -> g_xl
    gemm_kernel<<<(n + 127) / 128, 256>>>(x, Wr, n, 1);  // -> g_xr

    phaseA_kernel<<<4096, 256>>>(ea, We, att, Ei);
    phaseB_kernel<<<(n * 32 + 255) / 256, 256>>>(ea, We, att, out, n);

    diag_apply_kernel<<<512, 256>>>(out, total_out);
}

// round 11
// speedup vs baseline: 1.2319x; 1.2319x over previous
#include <cuda_runtime.h>
#include <cstdint>

#define D_IN   128
#define D_OUT  64
#define D_EDGE 11
#define NMAX   100000
#define EMAX   1000000
#define NEG_SLOPE 0.2f

// Scratch: ONLY referenced from device code (host-side use of a __device__
// symbol passes the host shadow address; ATS silently dereferences it).
__device__ float g_xl[(size_t)NMAX * D_OUT];     // x @ W_l
__device__ float g_xr[(size_t)NMAX * D_OUT];     // x @ W_r
__device__ float g_lsum[(size_t)NMAX * 12];      // [0..10]=sum attr, [11]=deg
__device__ float g_denom[NMAX];                  // sum of exp(logit) per dst
__device__ int2  g_sd[EMAX];                     // decoded (src, dst)
__device__ int   g_is64;
__device__ int   g_diag;

// ---------------------------------------------------------------------------
// Zero output + accumulators; detect int32 vs int64 edge_index (int64 values
// < 2^31 -> hi words of first 64 entries all zero).
// ---------------------------------------------------------------------------
__global__ void init_kernel(float* __restrict__ out, int out_total,
                            const int* __restrict__ ei, int E, int n) {
    int stride = gridDim.x * blockDim.x;
    int tid0 = blockIdx.x * blockDim.x + threadIdx.x;
    if (tid0 == 0) {
        g_diag = 0;
        int nz_hi = 0;
        int lim = (E > 64) ? 64 : E;
        for (int k = 0; k < lim; k++)
            if (ei[2 * k + 1] != 0) nz_hi++;
        g_is64 = (nz_hi == 0) ? 1 : 0;
    }
    for (int i = tid0; i < out_total; i += stride) out[i] = 0.0f;
    int total = n * 12;
    for (int i = tid0; i < total; i += stride) {
        g_lsum[i] = 0.0f;
        if (i < n) g_denom[i] = 0.0f;
    }
}

__global__ void set_diag_kernel(int bits) {
    if (threadIdx.x == 0) atomicOr(&g_diag, bits);
}

// Decode edge_index -> (src,dst) int2, bounds-checked.
__global__ void decode_kernel(const int* __restrict__ ei, int E, int n) {
    const int is64 = g_is64;
    int stride = gridDim.x * blockDim.x;
    for (int i = blockIdx.x * blockDim.x + threadIdx.x; i < E; i += stride) {
        int s, d;
        if (is64) { s = ei[2 * i];  d = ei[2 * E + 2 * i]; }
        else      { s = ei[i];      d = ei[E + i]; }
        if ((unsigned)s >= (unsigned)n) { atomicOr(&g_diag, 4); s = 0; }
        if ((unsigned)d >= (unsigned)n) { atomicOr(&g_diag, 4); d = 0; }
        g_sd[i] = make_int2(s, d);
    }
}

__global__ void diag_apply_kernel(float* __restrict__ out, int total) {
    const int diag = g_diag;
    if (diag == 0) return;
    float v = 0.f;
    if (diag & 4) v = 1e16f;
    if (diag & 8) v = 1e20f;
    int stride = gridDim.x * blockDim.x;
    for (int i = blockIdx.x * blockDim.x + threadIdx.x; i < total; i += stride)
        out[i] = v;
}

// ---------------------------------------------------------------------------
// Packed fp32x2 helpers (SASS FFMA2 — only reachable via PTX fma.rn.f32x2).
// ---------------------------------------------------------------------------
__device__ __forceinline__ void fma2(unsigned long long& d,
                                     unsigned long long a, unsigned long long b) {
    asm("fma.rn.f32x2 %0, %1, %2, %0;" : "+l"(d) : "l"(a), "l"(b));
}
__device__ __forceinline__ float2 unpack2(unsigned long long v) {
    unsigned int lo, hi;
    asm("mov.b64 {%0, %1}, %2;" : "=r"(lo), "=r"(hi) : "l"(v));
    return make_float2(__uint_as_float(lo), __uint_as_float(hi));
}

// ---------------------------------------------------------------------------
// GEMM via FFMA2: g_x{l,r}[n,64] = x[n,128] @ W[128,64].
// W staged k-pair-packed: sWp[kp*64+c] = {W[2kp][c], W[2kp+1][c]}. The x row
// float4 natively holds {x_k,x_k+1} per 64-bit half -> zero pack MOVs in the
// inner loop. Each FFMA2 accumulates even/odd-k partials per column; the
// epilogue adds the halves. Column groups g*16+2*cg make each LDS.128 hit
// banks 4cg..4cg+3 -> conflict-free. 64 FFMA2 per k-chunk (was 128 FFMA).
// ---------------------------------------------------------------------------
__global__ __launch_bounds__(256, 2) void gemm_kernel(
    const float* __restrict__ x, const float* __restrict__ W,
    int n, int which)
{
    float* __restrict__ out = which ? g_xr : g_xl;   // device-side symbol

    __shared__ __align__(16) unsigned long long sWp[64 * 64];  // 32 KB

    for (int i = threadIdx.x; i < 64 * 64; i += 256) {
        const int kp = i >> 6, c = i & 63;
        const unsigned int lo = __float_as_uint(W[(2 * kp)     * D_OUT + c]);
        const unsigned int hi = __float_as_uint(W[(2 * kp + 1) * D_OUT + c]);
        unsigned long long v;
        asm("mov.b64 %0, {%1, %2};" : "=l"(v) : "r"(lo), "r"(hi));
        sWp[i] = v;
    }
    __syncthreads();

    const int cg   = threadIdx.x & 7;
    const int rg   = threadIdx.x >> 3;
    const int row0 = blockIdx.x * 128 + rg * 4;

    unsigned long long acc2[4][8];   // [row][group*2 + colpair-half]
#pragma unroll
    for (int r = 0; r < 4; r++)
#pragma unroll
        for (int c = 0; c < 8; c++) acc2[r][c] = 0ull;

    for (int k = 0; k < D_IN; k += 4) {
        ulonglong2 xp[4];            // {x_k,x_k+1} and {x_k+2,x_k+3} per row
#pragma unroll
        for (int r = 0; r < 4; r++) {
            const int row = row0 + r;
            if (row < n)
                xp[r] = *reinterpret_cast<const ulonglong2*>(x + (size_t)row * D_IN + k);
            else { xp[r].x = 0ull; xp[r].y = 0ull; }
        }
        const int kp0 = k >> 1;
#pragma unroll
        for (int q = 0; q < 2; q++) {
#pragma unroll
            for (int g = 0; g < 4; g++) {
                const ulonglong2 w2 = *reinterpret_cast<const ulonglong2*>(
                    &sWp[(kp0 + q) * 64 + g * 16 + cg * 2]);
#pragma unroll
                for (int r = 0; r < 4; r++) {
                    const unsigned long long xq = q ? xp[r].y : xp[r].x;
                    fma2(acc2[r][g * 2],     xq, w2.x);
                    fma2(acc2[r][g * 2 + 1], xq, w2.y);
                }
            }
        }
    }

#pragma unroll
    for (int r = 0; r < 4; r++) {
        const int row = row0 + r;
        if (row < n) {
#pragma unroll
            for (int g = 0; g < 4; g++) {
                const float2 v0 = unpack2(acc2[r][g * 2]);
                const float2 v1 = unpack2(acc2[r][g * 2 + 1]);
                *reinterpret_cast<float2*>(out + (size_t)row * D_OUT + g * 16 + cg * 2) =
                    make_float2(v0.x + v0.y, v1.x + v1.y);
            }
        }
    }
}

// ---------------------------------------------------------------------------
// Edge pass (R9, measured-best): 2 edges per warp; 16 lanes x 4 cols.
// Attr row loaded one element per lane (single warp LDG), broadcast by shfl.
// lsum[0..10]+count packed -> one v4 RED by 3 lanes; denom by 1 lane.
// ---------------------------------------------------------------------------
__device__ __forceinline__ void red_add_v4(float* p, float a, float b, float c, float d) {
    asm volatile("red.global.add.v4.f32 [%0], {%1,%2,%3,%4};"
                 :: "l"(p), "f"(a), "f"(b), "f"(c), "f"(d) : "memory");
}

__global__ __launch_bounds__(256) void edge_kernel(
    const float* __restrict__ ea,
    const float* __restrict__ We, const float* __restrict__ att,
    float* __restrict__ out, int E)
{
    const int lane   = threadIdx.x & 31;
    const int half   = lane >> 4;
    const int sub    = lane & 15;
    const int cb     = sub * 4;
    const int hbase  = half << 4;
    const int warp   = (blockIdx.x * blockDim.x + threadIdx.x) >> 5;
    const int nwarps = (gridDim.x * blockDim.x) >> 5;

    float4 wev[D_EDGE];
#pragma unroll
    for (int j = 0; j < D_EDGE; j++)
        wev[j] = *reinterpret_cast<const float4*>(We + j * D_OUT + cb);
    const float4 at = *reinterpret_cast<const float4*>(att + cb);

    for (int e0 = warp * 2; e0 < E; e0 += nwarps * 2) {
        const int  e     = e0 + half;
        const bool valid = (e < E);
        const int  ec    = valid ? e : e0;

        const int2 sd = g_sd[ec];
        const float av = (sub < D_EDGE) ? __ldg(ea + (size_t)ec * D_EDGE + sub) : 0.f;

        const float4 vl = *reinterpret_cast<const float4*>(
            g_xl + (size_t)sd.x * D_OUT + cb);
        const float4 vr = *reinterpret_cast<const float4*>(
            g_xr + (size_t)sd.y * D_OUT + cb);

        float aj[D_EDGE];
#pragma unroll
        for (int j = 0; j < D_EDGE; j++)
            aj[j] = __shfl_sync(0xffffffffu, av, hbase + j);

        float e0c = 0.f, e1c = 0.f, e2c = 0.f, e3c = 0.f;
#pragma unroll
        for (int j = 0; j < D_EDGE; j++) {
            e0c += aj[j] * wev[j].x;
            e1c += aj[j] * wev[j].y;
            e2c += aj[j] * wev[j].z;
            e3c += aj[j] * wev[j].w;
        }

        float m0 = vl.x + vr.x + e0c;
        float m1 = vl.y + vr.y + e1c;
        float m2 = vl.z + vr.z + e2c;
        float m3 = vl.w + vr.w + e3c;
        m0 = (m0 >= 0.f) ? m0 : NEG_SLOPE * m0;
        m1 = (m1 >= 0.f) ? m1 : NEG_SLOPE * m1;
        m2 = (m2 >= 0.f) ? m2 : NEG_SLOPE * m2;
        m3 = (m3 >= 0.f) ? m3 : NEG_SLOPE * m3;
        float p = m0 * at.x + m1 * at.y + m2 * at.z + m3 * at.w;
#pragma unroll
        for (int o = 8; o > 0; o >>= 1)
            p += __shfl_xor_sync(0xffffffffu, p, o);
        const float ex = __expf(p);

        if (valid) {
            red_add_v4(out + (size_t)sd.y * D_OUT + cb,
                       ex * vl.x, ex * vl.y, ex * vl.z, ex * vl.w);
            if (sub < 3) {
                const float b0 = (sub == 0) ? aj[0] : (sub == 1) ? aj[4] : aj[8];
                const float b1 = (sub == 0) ? aj[1] : (sub == 1) ? aj[5] : aj[9];
                const float b2 = (sub == 0) ? aj[2] : (sub == 1) ? aj[6] : aj[10];
                const float b3 = (sub == 0) ? aj[3] : (sub == 1) ? aj[7] : 1.0f;
                red_add_v4(&g_lsum[(size_t)sd.y * 12 + sub * 4], b0, b1, b2, b3);
            } else if (sub == 3) {
                atomicAdd(&g_denom[sd.y], ex);
            }
        }
    }
}

// ---------------------------------------------------------------------------
// Finalize: 2 nodes per warp (16 lanes x 4 cols). Self-loop term + normalize.
// ---------------------------------------------------------------------------
__global__ __launch_bounds__(256) void final_kernel(
    const float* __restrict__ We, const float* __restrict__ att,
    float* __restrict__ out, int n)
{
    const int lane   = threadIdx.x & 31;
    const int half   = lane >> 4;
    const int sub    = lane & 15;
    const int cb     = sub * 4;
    const int warp   = (blockIdx.x * blockDim.x + threadIdx.x) >> 5;
    const int nwarps = (gridDim.x * blockDim.x) >> 5;

    float4 wev[D_EDGE];
#pragma unroll
    for (int j = 0; j < D_EDGE; j++)
        wev[j] = *reinterpret_cast<const float4*>(We + j * D_OUT + cb);
    const float4 at = *reinterpret_cast<const float4*>(att + cb);

    for (int i0 = warp * 2; i0 < n; i0 += nwarps * 2) {
        const int  i     = i0 + half;
        const bool valid = (i < n);
        const int  ic    = valid ? i : i0;

        const float4* lp = reinterpret_cast<const float4*>(g_lsum + (size_t)ic * 12);
        const float4 q0 = lp[0];
        const float4 q1 = lp[1];
        const float4 q2 = lp[2];
        const float inv_deg = 1.0f / fmaxf(q2.w, 1.0f);

        float e0c = q0.x*wev[0].x + q0.y*wev[1].x + q0.z*wev[2].x + q0.w*wev[3].x
                  + q1.x*wev[4].x + q1.y*wev[5].x + q1.z*wev[6].x + q1.w*wev[7].x
                  + q2.x*wev[8].x + q2.y*wev[9].x + q2.z*wev[10].x;
        float e1c = q0.x*wev[0].y + q0.y*wev[1].y + q0.z*wev[2].y + q0.w*wev[3].y
                  + q1.x*wev[4].y + q1.y*wev[5].y + q1.z*wev[6].y + q1.w*wev[7].y
                  + q2.x*wev[8].y + q2.y*wev[9].y + q2.z*wev[10].y;
        float e2c = q0.x*wev[0].z + q0.y*wev[1].z + q0.z*wev[2].z + q0.w*wev[3].z
                  + q1.x*wev[4].z + q1.y*wev[5].z + q1.z*wev[6].z + q1.w*wev[7].z
                  + q2.x*wev[8].z + q2.y*wev[9].z + q2.z*wev[10].z;
        float e3c = q0.x*wev[0].w + q0.y*wev[1].w + q0.z*wev[2].w + q0.w*wev[3].w
                  + q1.x*wev[4].w + q1.y*wev[5].w + q1.z*wev[6].w + q1.w*wev[7].w
                  + q2.x*wev[8].w + q2.y*wev[9].w + q2.z*wev[10].w;
        e0c *= inv_deg; e1c *= inv_deg; e2c *= inv_deg; e3c *= inv_deg;

        const float4 vl = *reinterpret_cast<const float4*>(g_xl + (size_t)ic * D_OUT + cb);
        const float4 vr = *reinterpret_cast<const float4*>(g_xr + (size_t)ic * D_OUT + cb);

        float m0 = vl.x + vr.x + e0c;
        float m1 = vl.y + vr.y + e1c;
        float m2 = vl.z + vr.z + e2c;
        float m3 = vl.w + vr.w + e3c;
        m0 = (m0 >= 0.f) ? m0 : NEG_SLOPE * m0;
        m1 = (m1 >= 0.f) ? m1 : NEG_SLOPE * m1;
        m2 = (m2 >= 0.f) ? m2 : NEG_SLOPE * m2;
        m3 = (m3 >= 0.f) ? m3 : NEG_SLOPE * m3;
        float p = m0 * at.x + m1 * at.y + m2 * at.z + m3 * at.w;
#pragma unroll
        for (int o = 8; o > 0; o >>= 1)
            p += __shfl_xor_sync(0xffffffffu, p, o);
        const float ex = __expf(p);

        if (valid) {
            const float invd = 1.0f / (g_denom[ic] + ex);
            float* op = out + (size_t)ic * D_OUT + cb;
            float4 o = *reinterpret_cast<float4*>(op);
            o.x = (o.x + ex * vl.x) * invd;
            o.y = (o.y + ex * vl.y) * invd;
            o.z = (o.z + ex * vl.z) * invd;
            o.w = (o.w + ex * vl.w) * invd;
            *reinterpret_cast<float4*>(op) = o;
        }
    }
}

// ---------------------------------------------------------------------------
extern "C" void kernel_launch(void* const* d_in, const int* in_sizes, int n_in,
                              void* d_out, int out_size)
{
    const float *x = nullptr, *ea = nullptr, *Wl = nullptr, *Wr = nullptr;
    const float *We = nullptr, *att = nullptr;
    const int   *ei = nullptr;
    long long E = 0;
    int n = 0;

    for (int i = 0; i < n_in; i++) {               // pass 1: edge_attr
        long long s = in_sizes[i];
        if (s > 100000 && s % D_EDGE == 0) { ea = (const float*)d_in[i]; E = s / D_EDGE; }
    }
    for (int i = 0; i < n_in; i++) {               // pass 2: everything else
        long long s = in_sizes[i];
        const void* p = d_in[i];
        if (p == (const void*)ea) continue;
        if      (E > 0 && (s == 2 * E || s == 4 * E)) { ei = (const int*)p; }
        else if (s == D_IN * D_OUT)   { if (!Wl) Wl = (const float*)p; else Wr = (const float*)p; }
        else if (s == D_EDGE * D_OUT) { We  = (const float*)p; }
        else if (s == D_OUT)          { att = (const float*)p; }
        else if (s > 100000 && s % D_IN == 0) { x = (const float*)p; n = (int)(s / D_IN); }
    }

    float* out = (float*)d_out;
    const int total_out = out_size;

    if (!x || !ea || !ei || !Wl || !Wr || !We || !att || n <= 0 || E <= 0 ||
        n > NMAX || E > EMAX) {
        set_diag_kernel<<<1, 32>>>(8);
        diag_apply_kernel<<<512, 256>>>(out, total_out);
        return;
    }
    const int Ei = (int)E;

    init_kernel<<<1024, 256>>>(out, total_out, ei, Ei, n);
    decode_kernel<<<512, 256>>>(ei, Ei, n);

    gemm_kernel<<<(n + 127) / 128, 256>>>(x, Wl, n, 0);  // -> g_xl
    gemm_kernel<<<(n + 127) / 128, 256>>>(x, Wr, n, 1);  // -> g_xr

    edge_kernel<<<4096, 256>>>(ea, We, att, out, Ei);
    final_kernel<<<2048, 256>>>(We, att, out, n);

    diag_apply_kernel<<<512, 256>>>(out, total_out);
}